// round 1
// baseline (speedup 1.0000x reference)
#include <cuda_runtime.h>
#include <cuda_bf16.h>
#include <cstdint>

#define Tn   4096
#define En   256
#define Hh   256
#define G4   1024     // 4*Hh
#define Ln   20
#define NCL  8        // CTAs per direction cluster
#define NEGV -10000.0f

// ---------------- scratch (device globals; no allocations allowed) ----------
__device__ float g_xs[Tn * En];                    // 4 MB
__device__ float g_zx[2][Tn * G4];                 // 32 MB
__device__ float g_h[2][Tn * Hh];                  // 8 MB
__device__ float g_feats[Tn * Ln];                 // 320 KB

// ---------------- helpers ----------------------------------------------------
__device__ __forceinline__ uint32_t smem_u32(const void* p) {
    uint32_t a;
    asm("{ .reg .u64 t; cvta.to.shared.u64 t, %1; cvt.u32.u64 %0, t; }"
        : "=r"(a) : "l"(p));
    return a;
}

#define FFMA2(acc, w, h) \
    asm("fma.rn.f32x2 %0, %1, %2, %0;" : "+l"(acc) : "l"(w), "l"(h))

#define FADD2(d, a, b) \
    asm("add.rn.f32x2 %0, %1, %2;" : "=l"(d) : "l"(a), "l"(b))

__device__ __forceinline__ float unpack_sum(unsigned long long v) {
    float lo, hi;
    asm("mov.b64 {%0, %1}, %2;" : "=f"(lo), "=f"(hi) : "l"(v));
    return lo + hi;
}

__device__ __forceinline__ void cluster_sync_() {
    asm volatile("barrier.cluster.arrive.aligned;" ::: "memory");
    asm volatile("barrier.cluster.wait.aligned;" ::: "memory");
}

__device__ __forceinline__ float fast_sigmoid(float x) {
    float e = __expf(-x);
    return __fdividef(1.0f, 1.0f + e);
}
__device__ __forceinline__ float fast_tanh(float x) {
    // tanh(x) = 2*sigmoid(2x) - 1
    float e = __expf(-2.0f * x);
    return __fdividef(1.0f - e, 1.0f + e);
}

// ---------------- K0: embedding gather ---------------------------------------
__global__ void gather_kernel(const int* __restrict__ x,
                              const float* __restrict__ emb) {
    int t = blockIdx.x;
    int row = x[t];
    const float4* src = (const float4*)(emb + (size_t)row * En);
    float4* dst = (float4*)(g_xs + (size_t)t * En);
    dst[threadIdx.x] = src[threadIdx.x];   // 64 threads * 16B = 1KB row
}

// ---------------- K1: Zx = xs @ W_ih^T + b_ih + b_hh (both dirs) -------------
// tile: 64 t x 64 rows, K chunks of 16. block 256 threads (16x16), 4x4 micro.
__global__ void zgemm_kernel(const float* __restrict__ wih_f,
                             const float* __restrict__ bih_f,
                             const float* __restrict__ bhh_f,
                             const float* __restrict__ wih_b,
                             const float* __restrict__ bih_b,
                             const float* __restrict__ bhh_b) {
    int dir = blockIdx.z;
    const float* W  = dir ? wih_b : wih_f;
    const float* b1 = dir ? bih_b : bih_f;
    const float* b2 = dir ? bhh_b : bhh_f;

    __shared__ float As[16][65];   // [k][t]
    __shared__ float Bs[16][65];   // [k][r]

    int tid = threadIdx.x;
    int t0 = blockIdx.x * 64;
    int r0 = blockIdx.y * 64;
    int tx = tid & 15;         // r group
    int ty = tid >> 4;         // t group
    int lk = tid & 15;         // loader k
    int lm = tid >> 4;         // loader row base

    float acc[4][4];
#pragma unroll
    for (int i = 0; i < 4; i++)
#pragma unroll
        for (int j = 0; j < 4; j++) acc[i][j] = 0.f;

    for (int k0 = 0; k0 < En; k0 += 16) {
#pragma unroll
        for (int i = 0; i < 4; i++) {
            int tt = lm + 16 * i;
            As[lk][tt] = g_xs[(size_t)(t0 + tt) * En + k0 + lk];
            int rr = lm + 16 * i;
            Bs[lk][rr] = W[(size_t)(r0 + rr) * En + k0 + lk];
        }
        __syncthreads();
#pragma unroll
        for (int k = 0; k < 16; k++) {
            float a[4], b[4];
#pragma unroll
            for (int i = 0; i < 4; i++) a[i] = As[k][ty + 16 * i];
#pragma unroll
            for (int j = 0; j < 4; j++) b[j] = Bs[k][tx + 16 * j];
#pragma unroll
            for (int i = 0; i < 4; i++)
#pragma unroll
                for (int j = 0; j < 4; j++) acc[i][j] = fmaf(a[i], b[j], acc[i][j]);
        }
        __syncthreads();
    }
#pragma unroll
    for (int i = 0; i < 4; i++) {
        int tt = t0 + ty + 16 * i;
#pragma unroll
        for (int j = 0; j < 4; j++) {
            int rr = r0 + tx + 16 * j;
            g_zx[dir][(size_t)tt * G4 + rr] = acc[i][j] + b1[rr] + b2[rr];
        }
    }
}

// ---------------- K2: bidirectional LSTM, 2 clusters of 8 CTAs ---------------
// CTA r owns h slice [r*32, r*32+32), i.e. 128 gate rows, weights in registers.
__global__ void __cluster_dims__(NCL, 1, 1) __launch_bounds__(256, 1)
lstm_kernel(const float* __restrict__ whh_f,
            const float* __restrict__ whh_b,
            const float* __restrict__ h0,
            const float* __restrict__ c0) {
    __shared__ __align__(16) float h_s[2][Hh];
    __shared__ float z_s[128];

    int tid = threadIdx.x;
    int cta = blockIdx.x;
    int dir = cta >> 3;
    int r   = cta & 7;

    const float* W = dir ? whh_b : whh_f;
    const float* Z = g_zx[dir];
    float* H = g_h[dir];

    int lr   = tid >> 1;     // local row 0..127
    int half = tid & 1;      // column half
    int gate = lr >> 5;
    int j32  = lr & 31;
    int grow = gate * 256 + r * 32 + j32;   // global gate row

    // Load 128 weights/thread into registers as 32 x ulonglong2 (f32x2 pairs)
    ulonglong2 wreg[32];
    {
        const ulonglong2* wp =
            (const ulonglong2*)(W + (size_t)grow * Hh + half * 128);
#pragma unroll
        for (int i = 0; i < 32; i++) wreg[i] = wp[i];
    }

    // init state
    h_s[0][tid] = h0[dir * Hh + tid];
    float c = 0.f;
    if (tid < 32) c = c0[dir * Hh + r * 32 + tid];
    __syncthreads();
    cluster_sync_();

    unsigned p = 0;
    for (int s = 0; s < Tn; s++) {
        int t = dir ? (Tn - 1 - s) : s;

        // prefetch Zx for this step (used after the matvec)
        float zxv = 0.f;
        if (half == 0) zxv = __ldg(&Z[(size_t)t * G4 + grow]);

        const ulonglong2* hp = (const ulonglong2*)&h_s[p][half * 128];
        unsigned long long a[8] = {0, 0, 0, 0, 0, 0, 0, 0};
#pragma unroll
        for (int i = 0; i < 32; i++) {
            ulonglong2 hv = hp[i];
            FFMA2(a[(2 * i) & 7], wreg[i].x, hv.x);
            FFMA2(a[(2 * i + 1) & 7], wreg[i].y, hv.y);
        }
        unsigned long long b0, b1, b2, b3, t0_, t1_, t2_;
        FADD2(b0, a[0], a[4]); FADD2(b1, a[1], a[5]);
        FADD2(b2, a[2], a[6]); FADD2(b3, a[3], a[7]);
        FADD2(t0_, b0, b2); FADD2(t1_, b1, b3); FADD2(t2_, t0_, t1_);
        float v = unpack_sum(t2_);
        v += __shfl_xor_sync(0xffffffffu, v, 1);
        if (half == 0) z_s[lr] = v + zxv;
        __syncthreads();

        if (tid < 32) {
            float zi = z_s[tid];
            float zf = z_s[32 + tid];
            float zg = z_s[64 + tid];
            float zo = z_s[96 + tid];
            float ig = fast_sigmoid(zi);
            float fg = fast_sigmoid(zf);
            float og = fast_sigmoid(zo);
            float gg = fast_tanh(zg);
            c = fg * c + ig * gg;
            float hn = og * fast_tanh(c);
            H[(size_t)t * Hh + r * 32 + tid] = hn;

            unsigned np = p ^ 1;
            uint32_t laddr = smem_u32(&h_s[np][r * 32 + tid]);
#pragma unroll
            for (int rr = 0; rr < NCL; rr++) {
                uint32_t raddr;
                asm("mapa.shared::cluster.u32 %0, %1, %2;"
                    : "=r"(raddr) : "r"(laddr), "r"(rr));
                asm volatile("st.shared::cluster.f32 [%0], %1;"
                             :: "r"(raddr), "f"(hn) : "memory");
            }
        }
        cluster_sync_();
        p ^= 1;
    }
}

// ---------------- K3: feats = [h_f, h_b] @ w_out^T + b_out -------------------
__global__ void feats_kernel(const float* __restrict__ wout,
                             const float* __restrict__ bout) {
    int t = blockIdx.x;
    int w = threadIdx.x >> 5;   // label
    int lane = threadIdx.x & 31;
    const float* h1 = g_h[0] + (size_t)t * Hh;
    const float* h2 = g_h[1] + (size_t)t * Hh;
    const float* wr = wout + (size_t)w * 512;
    float sum = 0.f;
#pragma unroll
    for (int k = lane; k < 256; k += 32) sum = fmaf(h1[k], wr[k], sum);
#pragma unroll
    for (int k = lane; k < 256; k += 32) sum = fmaf(h2[k], wr[256 + k], sum);
#pragma unroll
    for (int o = 16; o; o >>= 1) sum += __shfl_xor_sync(0xffffffffu, sum, o);
    if (lane == 0) g_feats[(size_t)t * Ln + w] = sum + bout[w];
}

// ---------------- K4: Viterbi + backtrack (single warp) ----------------------
__global__ void viterbi_kernel(const float* __restrict__ trans,
                               float* __restrict__ out, int out_size) {
    extern __shared__ unsigned char bp[];   // [Tn][Ln]
    int lane = threadIdx.x;
    int to = lane;
    bool act = (to < Ln);

    float tr[Ln];
#pragma unroll
    for (int f = 0; f < Ln; f++) tr[f] = act ? trans[to * Ln + f] : -1e30f;
    float trstop = act ? trans[19 * Ln + to] : -1e30f;

    float alpha = (to == 18) ? 0.f : NEGV;

    float fr0 = act ? g_feats[0 * Ln + to] : 0.f;
    float fr1 = act ? g_feats[1 * Ln + to] : 0.f;

    for (int t = 0; t < Tn; t++) {
        float frn = (act && t + 2 < Tn) ? g_feats[(size_t)(t + 2) * Ln + to] : 0.f;

        float s[Ln];
#pragma unroll
        for (int f = 0; f < Ln; f++)
            s[f] = __shfl_sync(0xffffffffu, alpha, f) + tr[f];

        // tree max (keep s[] intact for argmax mask)
        float m[10];
#pragma unroll
        for (int i = 0; i < 10; i++) m[i] = fmaxf(s[i], s[i + 10]);
#pragma unroll
        for (int i = 0; i < 5; i++) m[i] = fmaxf(m[i], m[i + 5]);
        float best = fmaxf(fmaxf(fmaxf(m[0], m[1]), fmaxf(m[2], m[3])), m[4]);

        unsigned msk = 0;
#pragma unroll
        for (int f = 0; f < Ln; f++)
            msk |= (s[f] == best) ? (1u << f) : 0u;
        int arg = __ffs(msk) - 1;   // first (lowest) index, matches jnp.argmax

        if (act) bp[(size_t)t * Ln + to] = (unsigned char)arg;
        alpha = best + fr0;
        fr0 = fr1;
        fr1 = frn;
    }

    float fin = act ? (alpha + trstop) : -1e30f;
    float best = fin;
#pragma unroll
    for (int o = 16; o; o >>= 1) best = fmaxf(best, __shfl_xor_sync(0xffffffffu, best, o));
    unsigned msk = __ballot_sync(0xffffffffu, fin == best);
    int best_last = __ffs(msk) - 1;

    if (lane == 0) {
        float* po = out;
        if (out_size >= Tn + 1) { out[0] = best; po = out + 1; }
        int cur = best_last;
        po[Tn - 1] = (float)cur;
        for (int t = Tn - 1; t >= 1; t--) {
            cur = bp[(size_t)t * Ln + cur];
            po[t - 1] = (float)cur;
        }
        if (out_size == 1) out[0] = best;
    }
}

// ---------------- launch ------------------------------------------------------
extern "C" void kernel_launch(void* const* d_in, const int* in_sizes, int n_in,
                              void* d_out, int out_size) {
    const int*   x      = (const int*)  d_in[0];
    const float* emb    = (const float*)d_in[1];
    const float* wih_f  = (const float*)d_in[2];
    const float* whh_f  = (const float*)d_in[3];
    const float* bih_f  = (const float*)d_in[4];
    const float* bhh_f  = (const float*)d_in[5];
    const float* wih_b  = (const float*)d_in[6];
    const float* whh_b  = (const float*)d_in[7];
    const float* bih_b  = (const float*)d_in[8];
    const float* bhh_b  = (const float*)d_in[9];
    const float* wout   = (const float*)d_in[10];
    const float* bout   = (const float*)d_in[11];
    const float* trans  = (const float*)d_in[12];
    const float* h0     = (const float*)d_in[13];
    const float* c0     = (const float*)d_in[14];
    float* out = (float*)d_out;

    gather_kernel<<<Tn, 64>>>(x, emb);

    dim3 zg(Tn / 64, G4 / 64, 2);
    zgemm_kernel<<<zg, 256>>>(wih_f, bih_f, bhh_f, wih_b, bih_b, bhh_b);

    lstm_kernel<<<2 * NCL, 256>>>(whh_f, whh_b, h0, c0);

    feats_kernel<<<Tn, Ln * 32>>>(wout, bout);

    int vit_smem = Tn * Ln;  // 80 KB backpointers
    cudaFuncSetAttribute(viterbi_kernel,
                         cudaFuncAttributeMaxDynamicSharedMemorySize, vit_smem);
    viterbi_kernel<<<1, 32, vit_smem>>>(trans, out, out_size);
}

// round 3
// speedup vs baseline: 1.8647x; 1.8647x over previous
#include <cuda_runtime.h>
#include <cuda_bf16.h>
#include <cstdint>

#define Tn   4096
#define En   256
#define Hh   256
#define G4   1024     // 4*Hh
#define Ln   20
#define NCL  8        // CTAs per direction cluster
#define NEGV -10000.0f

// ---------------- scratch (device globals; no allocations allowed) ----------
__device__ float g_xs[Tn * En];                    // 4 MB
__device__ float g_zx[2][Tn * G4];                 // 32 MB
__device__ float g_h[2][Tn * Hh];                  // 8 MB
__device__ float g_feats[Tn * Ln];                 // 320 KB

// ---------------- helpers ----------------------------------------------------
__device__ __forceinline__ uint32_t smem_u32(const void* p) {
    uint32_t a;
    asm("{ .reg .u64 t; cvta.to.shared.u64 t, %1; cvt.u32.u64 %0, t; }"
        : "=r"(a) : "l"(p));
    return a;
}

#define FFMA2(acc, w, h) \
    asm("fma.rn.f32x2 %0, %1, %2, %0;" : "+l"(acc) : "l"(w), "l"(h))

#define FADD2(d, a, b) \
    asm("add.rn.f32x2 %0, %1, %2;" : "=l"(d) : "l"(a), "l"(b))

__device__ __forceinline__ float unpack_sum(unsigned long long v) {
    float lo, hi;
    asm("mov.b64 {%0, %1}, %2;" : "=f"(lo), "=f"(hi) : "l"(v));
    return lo + hi;
}

__device__ __forceinline__ void cluster_sync_() {
    asm volatile("barrier.cluster.arrive.aligned;" ::: "memory");
    asm volatile("barrier.cluster.wait.aligned;" ::: "memory");
}

// mbarrier wait on phase parity, cluster-scope acquire (remote st.async data).
__device__ __forceinline__ void wait_parity(uint32_t mbar, unsigned parity) {
    unsigned done = 0;
    asm volatile(
        "{ .reg .pred p;\n\t"
        "mbarrier.try_wait.parity.acquire.cluster.shared::cta.b64 p, [%1], %2;\n\t"
        "selp.b32 %0, 1, 0, p; }"
        : "=r"(done) : "r"(mbar), "r"(parity) : "memory");
    while (!done) {
        asm volatile(
            "{ .reg .pred p;\n\t"
            "mbarrier.try_wait.parity.acquire.cluster.shared::cta.b64 p, [%1], %2, 0x989680;\n\t"
            "selp.b32 %0, 1, 0, p; }"
            : "=r"(done) : "r"(mbar), "r"(parity) : "memory");
    }
}

__device__ __forceinline__ float fast_sigmoid(float x) {
    float e = __expf(-x);
    return __fdividef(1.0f, 1.0f + e);
}
__device__ __forceinline__ float fast_tanh(float x) {
    float e = __expf(-2.0f * x);
    return __fdividef(1.0f - e, 1.0f + e);
}

// ---------------- K0: embedding gather ---------------------------------------
__global__ void gather_kernel(const int* __restrict__ x,
                              const float* __restrict__ emb) {
    int t = blockIdx.x;
    int row = x[t];
    const float4* src = (const float4*)(emb + (size_t)row * En);
    float4* dst = (float4*)(g_xs + (size_t)t * En);
    dst[threadIdx.x] = src[threadIdx.x];
}

// ---------------- K1: Zx = xs @ W_ih^T + b_ih + b_hh (both dirs) -------------
__global__ void zgemm_kernel(const float* __restrict__ wih_f,
                             const float* __restrict__ bih_f,
                             const float* __restrict__ bhh_f,
                             const float* __restrict__ wih_b,
                             const float* __restrict__ bih_b,
                             const float* __restrict__ bhh_b) {
    int dir = blockIdx.z;
    const float* W  = dir ? wih_b : wih_f;
    const float* b1 = dir ? bih_b : bih_f;
    const float* b2 = dir ? bhh_b : bhh_f;

    __shared__ float As[16][65];
    __shared__ float Bs[16][65];

    int tid = threadIdx.x;
    int t0 = blockIdx.x * 64;
    int r0 = blockIdx.y * 64;
    int tx = tid & 15;
    int ty = tid >> 4;
    int lk = tid & 15;
    int lm = tid >> 4;

    float acc[4][4];
#pragma unroll
    for (int i = 0; i < 4; i++)
#pragma unroll
        for (int j = 0; j < 4; j++) acc[i][j] = 0.f;

    for (int k0 = 0; k0 < En; k0 += 16) {
#pragma unroll
        for (int i = 0; i < 4; i++) {
            int tt = lm + 16 * i;
            As[lk][tt] = g_xs[(size_t)(t0 + tt) * En + k0 + lk];
            int rr = lm + 16 * i;
            Bs[lk][rr] = W[(size_t)(r0 + rr) * En + k0 + lk];
        }
        __syncthreads();
#pragma unroll
        for (int k = 0; k < 16; k++) {
            float a[4], b[4];
#pragma unroll
            for (int i = 0; i < 4; i++) a[i] = As[k][ty + 16 * i];
#pragma unroll
            for (int j = 0; j < 4; j++) b[j] = Bs[k][tx + 16 * j];
#pragma unroll
            for (int i = 0; i < 4; i++)
#pragma unroll
                for (int j = 0; j < 4; j++) acc[i][j] = fmaf(a[i], b[j], acc[i][j]);
        }
        __syncthreads();
    }
#pragma unroll
    for (int i = 0; i < 4; i++) {
        int tt = t0 + ty + 16 * i;
#pragma unroll
        for (int j = 0; j < 4; j++) {
            int rr = r0 + tx + 16 * j;
            g_zx[dir][(size_t)tt * G4 + rr] = acc[i][j] + b1[rr] + b2[rr];
        }
    }
}

// ---------------- K2: bidirectional LSTM, 2 clusters of 8 CTAs ---------------
// CTA r owns h slice [r*32, r*32+32) (128 gate rows), weights in registers.
// Per-step sync: st.async + tx-counting mbarriers (NO cluster.sync / L1 flush).
__global__ void __cluster_dims__(NCL, 1, 1) __launch_bounds__(256, 1)
lstm_kernel(const float* __restrict__ whh_f,
            const float* __restrict__ whh_b,
            const float* __restrict__ h0,
            const float* __restrict__ c0) {
    __shared__ __align__(16) float hbuf[2][Hh];      // double-buffered h state
    __shared__ __align__(8) unsigned long long fullbar[2];
    __shared__ float z_s[128];

    int tid = threadIdx.x;
    int cta = blockIdx.x;
    int dir = cta >> 3;
    int r   = cta & 7;

    const float* W = dir ? whh_b : whh_f;
    const float* Z = g_zx[dir];
    float* H = g_h[dir];

    int lr   = tid >> 1;     // local row 0..127
    int half = tid & 1;      // column half
    int gate = lr >> 5;
    int j32  = lr & 31;
    int grow = gate * 256 + r * 32 + j32;   // global gate row

    // 128 weights/thread in registers (32 x f32x2-pair)
    ulonglong2 wreg[32];
    {
        const ulonglong2* wp =
            (const ulonglong2*)(W + (size_t)grow * Hh + half * 128);
#pragma unroll
        for (int i = 0; i < 32; i++) wreg[i] = wp[i];
    }

    // init barriers + state
    uint32_t bar0 = smem_u32(&fullbar[0]);
    if (tid == 0) {
        asm volatile("mbarrier.init.shared.b64 [%0], 1;" :: "r"(bar0) : "memory");
        asm volatile("mbarrier.init.shared.b64 [%0], 1;" :: "r"(bar0 + 8) : "memory");
    }
    hbuf[0][tid] = h0[dir * Hh + tid];
    float c = 0.f;
    if (tid < 32) c = c0[dir * Hh + r * 32 + tid];
    __syncthreads();
    cluster_sync_();   // barriers + hbuf[0] visible cluster-wide before any st.async

    // initial expect_tx for first use of each barrier (1024 B = 8 CTA x 32 x 4B)
    if (tid == 32) {
        asm volatile("mbarrier.arrive.expect_tx.shared.b64 _, [%0], 1024;"
                     :: "r"(bar0) : "memory");
        asm volatile("mbarrier.arrive.expect_tx.shared.b64 _, [%0], 1024;"
                     :: "r"(bar0 + 8) : "memory");
    }

    // precompute remote addresses (mapa preserves offsets within a CTA)
    uint32_t rbuf0[NCL], rbar0[NCL];
    if (tid < 32) {
        uint32_t lbuf = smem_u32(&hbuf[0][r * 32 + tid]);
#pragma unroll
        for (int rr = 0; rr < NCL; rr++) {
            asm("mapa.shared::cluster.u32 %0, %1, %2;"
                : "=r"(rbuf0[rr]) : "r"(lbuf), "r"(rr));
            asm("mapa.shared::cluster.u32 %0, %1, %2;"
                : "=r"(rbar0[rr]) : "r"(bar0), "r"(rr));
        }
    }

    unsigned ph0 = 0, ph1 = 0;
    for (int s = 0; s < Tn; s++) {
        int t = dir ? (Tn - 1 - s) : s;
        int b = s & 1;

        if (s > 0) {
            if (b) { wait_parity(bar0 + 8, ph1); if (tid == 32) { ph1 ^= 1;
                asm volatile("mbarrier.arrive.expect_tx.shared.b64 _, [%0], 1024;"
                             :: "r"(bar0 + 8) : "memory"); } else ph1 ^= 1; }
            else   { wait_parity(bar0, ph0);     if (tid == 32) { ph0 ^= 1;
                asm volatile("mbarrier.arrive.expect_tx.shared.b64 _, [%0], 1024;"
                             :: "r"(bar0) : "memory"); } else ph0 ^= 1; }
        }

        // prefetch Zx (used after matvec)
        float zxv = 0.f;
        if (half == 0) zxv = __ldg(&Z[(size_t)t * G4 + grow]);

        const ulonglong2* hp = (const ulonglong2*)&hbuf[b][half * 128];
        unsigned long long a[8] = {0, 0, 0, 0, 0, 0, 0, 0};
#pragma unroll
        for (int i = 0; i < 32; i++) {
            ulonglong2 hv = hp[i];
            FFMA2(a[(2 * i) & 7], wreg[i].x, hv.x);
            FFMA2(a[(2 * i + 1) & 7], wreg[i].y, hv.y);
        }
        unsigned long long b0_, b1_, b2_, b3_, t0_, t1_, t2_;
        FADD2(b0_, a[0], a[4]); FADD2(b1_, a[1], a[5]);
        FADD2(b2_, a[2], a[6]); FADD2(b3_, a[3], a[7]);
        FADD2(t0_, b0_, b2_); FADD2(t1_, b1_, b3_); FADD2(t2_, t0_, t1_);
        float v = unpack_sum(t2_);
        v += __shfl_xor_sync(0xffffffffu, v, 1);
        if (half == 0) z_s[lr] = v + zxv;
        __syncthreads();

        if (tid < 32) {
            float zi = z_s[tid];
            float zf = z_s[32 + tid];
            float zg = z_s[64 + tid];
            float zo = z_s[96 + tid];
            float ig = fast_sigmoid(zi);
            float fg = fast_sigmoid(zf);
            float og = fast_sigmoid(zo);
            float gg = fast_tanh(zg);
            c = fg * c + ig * gg;
            float hn = og * fast_tanh(c);
            H[(size_t)t * Hh + r * 32 + tid] = hn;

            if (s != Tn - 1) {
                int nb = (s + 1) & 1;
                uint32_t hbits = __float_as_uint(hn);
                uint32_t boff = (uint32_t)nb << 10;   // hbuf stride 1024 B
                uint32_t moff = (uint32_t)nb << 3;    // bar stride 8 B
#pragma unroll
                for (int rr = 0; rr < NCL; rr++) {
                    asm volatile(
                        "st.async.shared::cluster.mbarrier::complete_tx::bytes.b32"
                        " [%0], %1, [%2];"
                        :: "r"(rbuf0[rr] + boff), "r"(hbits), "r"(rbar0[rr] + moff)
                        : "memory");
                }
            }
        }
    }
    cluster_sync_();   // teardown: no CTA exits while peers may map its smem
}

// ---------------- K3: feats = [h_f, h_b] @ w_out^T + b_out -------------------
__global__ void feats_kernel(const float* __restrict__ wout,
                             const float* __restrict__ bout) {
    int t = blockIdx.x;
    int w = threadIdx.x >> 5;
    int lane = threadIdx.x & 31;
    const float* h1 = g_h[0] + (size_t)t * Hh;
    const float* h2 = g_h[1] + (size_t)t * Hh;
    const float* wr = wout + (size_t)w * 512;
    float sum = 0.f;
#pragma unroll
    for (int k = lane; k < 256; k += 32) sum = fmaf(h1[k], wr[k], sum);
#pragma unroll
    for (int k = lane; k < 256; k += 32) sum = fmaf(h2[k], wr[256 + k], sum);
#pragma unroll
    for (int o = 16; o; o >>= 1) sum += __shfl_xor_sync(0xffffffffu, sum, o);
    if (lane == 0) g_feats[(size_t)t * Ln + w] = sum + bout[w];
}

// ---------------- K4: Viterbi + backtrack (single warp) ----------------------
__global__ void viterbi_kernel(const float* __restrict__ trans,
                               float* __restrict__ out, int out_size) {
    extern __shared__ unsigned char bp[];   // [Tn][Ln]
    int lane = threadIdx.x;
    int to = lane;
    bool act = (to < Ln);

    float tr[Ln];
#pragma unroll
    for (int f = 0; f < Ln; f++) tr[f] = act ? trans[to * Ln + f] : -1e30f;
    float trstop = act ? trans[19 * Ln + to] : -1e30f;

    float alpha = (to == 18) ? 0.f : NEGV;

    float fr0 = act ? g_feats[0 * Ln + to] : 0.f;
    float fr1 = act ? g_feats[1 * Ln + to] : 0.f;

    for (int t = 0; t < Tn; t++) {
        float frn = (act && t + 2 < Tn) ? g_feats[(size_t)(t + 2) * Ln + to] : 0.f;

        float s[Ln];
#pragma unroll
        for (int f = 0; f < Ln; f++)
            s[f] = __shfl_sync(0xffffffffu, alpha, f) + tr[f];

        float m[10];
#pragma unroll
        for (int i = 0; i < 10; i++) m[i] = fmaxf(s[i], s[i + 10]);
#pragma unroll
        for (int i = 0; i < 5; i++) m[i] = fmaxf(m[i], m[i + 5]);
        float best = fmaxf(fmaxf(fmaxf(m[0], m[1]), fmaxf(m[2], m[3])), m[4]);

        unsigned msk = 0;
#pragma unroll
        for (int f = 0; f < Ln; f++)
            msk |= (s[f] == best) ? (1u << f) : 0u;
        int arg = __ffs(msk) - 1;

        if (act) bp[(size_t)t * Ln + to] = (unsigned char)arg;
        alpha = best + fr0;
        fr0 = fr1;
        fr1 = frn;
    }

    float fin = act ? (alpha + trstop) : -1e30f;
    float best = fin;
#pragma unroll
    for (int o = 16; o; o >>= 1) best = fmaxf(best, __shfl_xor_sync(0xffffffffu, best, o));
    unsigned msk = __ballot_sync(0xffffffffu, fin == best);
    int best_last = __ffs(msk) - 1;

    if (lane == 0) {
        float* po = out;
        if (out_size >= Tn + 1) { out[0] = best; po = out + 1; }
        int cur = best_last;
        po[Tn - 1] = (float)cur;
        for (int t = Tn - 1; t >= 1; t--) {
            cur = bp[(size_t)t * Ln + cur];
            po[t - 1] = (float)cur;
        }
        if (out_size == 1) out[0] = best;
    }
}

// ---------------- launch ------------------------------------------------------
extern "C" void kernel_launch(void* const* d_in, const int* in_sizes, int n_in,
                              void* d_out, int out_size) {
    const int*   x      = (const int*)  d_in[0];
    const float* emb    = (const float*)d_in[1];
    const float* wih_f  = (const float*)d_in[2];
    const float* whh_f  = (const float*)d_in[3];
    const float* bih_f  = (const float*)d_in[4];
    const float* bhh_f  = (const float*)d_in[5];
    const float* wih_b  = (const float*)d_in[6];
    const float* whh_b  = (const float*)d_in[7];
    const float* bih_b  = (const float*)d_in[8];
    const float* bhh_b  = (const float*)d_in[9];
    const float* wout   = (const float*)d_in[10];
    const float* bout   = (const float*)d_in[11];
    const float* trans  = (const float*)d_in[12];
    const float* h0     = (const float*)d_in[13];
    const float* c0     = (const float*)d_in[14];
    float* out = (float*)d_out;

    gather_kernel<<<Tn, 64>>>(x, emb);

    dim3 zg(Tn / 64, G4 / 64, 2);
    zgemm_kernel<<<zg, 256>>>(wih_f, bih_f, bhh_f, wih_b, bih_b, bhh_b);

    lstm_kernel<<<2 * NCL, 256>>>(whh_f, whh_b, h0, c0);

    feats_kernel<<<Tn, Ln * 32>>>(wout, bout);

    int vit_smem = Tn * Ln;
    cudaFuncSetAttribute(viterbi_kernel,
                         cudaFuncAttributeMaxDynamicSharedMemorySize, vit_smem);
    viterbi_kernel<<<1, 32, vit_smem>>>(trans, out, out_size);
}